// round 17
// baseline (speedup 1.0000x reference)
#include <cuda_runtime.h>
#include <cstdint>

#define N_NODES 48
#define N_EDGES 192
#define DIM     1024
#define NN      (N_NODES * N_NODES)   // 2304
#define EE      (N_EDGES * N_EDGES)   // 36864
#define OUT_DIM NN                    // 2304
#define N4      ((OUT_DIM * OUT_DIM) / 4)   // 1,327,104 float4
#define GEMM_BLOCKS 144               // 12 x 12 tiles of 16x16 outputs
#define MP_BLOCKS   96
#define MAIN_BLOCKS (GEMM_BLOCKS + MP_BLOCKS)  // 240
#define CB (2 * DIM)                  // 2048 coeff blocks (1 row each)
#define CT 128
#define BS_STRIDE 516                 // 16B-aligned, 2-way-max bank pattern

// Scratch (no cudaMalloc allowed)
__device__ float g_cn[DIM];
__device__ float g_ce[DIM];

__device__ __forceinline__ float softplus_act(float x) {
    // relu(softplus(x) - 0.5)
    float sp = (x > 20.f) ? x : log1pf(expf(x));
    float v = sp - 0.5f;
    return v > 0.f ? v : 0.f;
}

// ---------------------------------------------------------------------------
// Kernel 1: coeff = tanh(W @ gw + b), block-per-row (2048 blocks x 128 thr,
// proven R5 shape) + the FULL 21MB zero-fill spread across all blocks
// (stores drain while each block's weight loads are in flight).
// ---------------------------------------------------------------------------
__global__ void __launch_bounds__(CT)
k_coeff(const float* __restrict__ Wn, const float* __restrict__ bn,
        const float* __restrict__ We, const float* __restrict__ be,
        const float* __restrict__ gw, float4* __restrict__ out4) {
    int t = threadIdx.x;
    int row = blockIdx.x;            // 0..2047

    // zero-fill slice
    {
        float4 z = make_float4(0.f, 0.f, 0.f, 0.f);
        for (int i = row * CT + t; i < N4; i += CB * CT)
            out4[i] = z;
    }

    const float* W;
    const float* b;
    float* outp;
    int r;
    if (row < DIM) { W = Wn; b = bn; outp = g_cn; r = row; }
    else           { W = We; b = be; outp = g_ce; r = row - DIM; }

    const float4* Wr = (const float4*)(W + (size_t)r * DIM);
    const float4* g4 = (const float4*)gw;
    float acc = 0.f;
#pragma unroll
    for (int i = 0; i < 2; i++) {
        int k = t + CT * i;                      // 0..255 float4
        float4 a = Wr[k], g = g4[k];
        acc += a.x * g.x + a.y * g.y + a.z * g.z + a.w * g.w;
    }
#pragma unroll
    for (int o = 16; o; o >>= 1) acc += __shfl_xor_sync(0xffffffffu, acc, o);

    __shared__ float sred[CT / 32];
    if ((t & 31) == 0) sred[t >> 5] = acc;
    __syncthreads();
    if (t == 0) {
        float s = sred[0] + sred[1] + sred[2] + sred[3];
        outp[r] = tanhf(s + b[r]);
    }
}

// ---------------------------------------------------------------------------
// Kernel 2: blocks 0..143 -> Me FULL-K (no split-K): 16x16 outputs per
// block, one output per thread (K=1024 dot). B-tile (16 rows, ce folded)
// staged in smem in 2 phases of 512 k; A rows read through L1 (2 distinct
// addresses per warp -> broadcast). Each block activates and atomicAdds its
// 256 values straight into M -- no partial buffers, no third kernel.
// blocks 144..239 -> Mp (48x48), diagonal added directly (M zeroed by K1).
// ---------------------------------------------------------------------------
__global__ void __launch_bounds__(256)
k_main(const float* __restrict__ ef1, const float* __restrict__ ef2,
       const float* __restrict__ x1, const float* __restrict__ x2,
       const int* __restrict__ ei1, const int* __restrict__ ei2,
       float* __restrict__ M) {
    int t = threadIdx.x;
    int b = blockIdx.x;

    if (b < GEMM_BLOCKS) {
        __shared__ float Bs[16][BS_STRIDE];   // 16 rows x 512 k (+pad) = 33KB

        int by = b / 12, bx = b % 12;
        int mloc = t >> 4;                    // 0..15  (this thread's Me row)
        int n    = t & 15;                    //        (this thread's Me col)
        int gm = by * 16 + mloc;
        int gn = bx * 16 + n;
        const float4* Arow = (const float4*)(ef1 + (size_t)gm * DIM);

        float4 acc = make_float4(0.f, 0.f, 0.f, 0.f);  // 4 independent chains

#pragma unroll 1
        for (int ph = 0; ph < 2; ph++) {
            int kb4 = ph * 128;               // float4 base of this phase
            // ---- fill Bs with ce-folded B tile (coalesced)
            {
                int rr = t >> 4, c = t & 15;  // 16 threads per row
                const float4* Brow =
                    (const float4*)(ef2 + (size_t)(bx * 16 + rr) * DIM) + kb4;
                const float4* C4 = (const float4*)g_ce + kb4;
#pragma unroll
                for (int i = 0; i < 8; i++) {
                    int k4 = c + 16 * i;      // 0..127
                    float4 bv = Brow[k4];
                    float4 cv = C4[k4];
                    bv.x *= cv.x; bv.y *= cv.y; bv.z *= cv.z; bv.w *= cv.w;
                    *(float4*)&Bs[rr][4 * k4] = bv;
                }
            }
            __syncthreads();
            // ---- compute 512 k
            const float4* Ap = Arow + kb4;
#pragma unroll 4
            for (int k4 = 0; k4 < 128; k4++) {
                float4 a  = Ap[k4];
                float4 bv = *(const float4*)&Bs[n][4 * k4];
                acc.x += a.x * bv.x;
                acc.y += a.y * bv.y;
                acc.z += a.z * bv.z;
                acc.w += a.w * bv.w;
            }
            if (ph == 0) __syncthreads();     // before Bs refill
        }

        float s = (acc.x + acc.y) + (acc.z + acc.w);
        float v = softplus_act(s);
        // e = gm*192+gn; value Me[gm][gn] ->
        //   M[ei2h[gm]*48 + ei1h[gn], ei2t[gm]*48 + ei1t[gn]] += v
        if (v > 0.f) {
            int rr = ei2[gm] * N_NODES + ei1[gn];
            int cc = ei2[N_EDGES + gm] * N_NODES + ei1[N_EDGES + gn];
            atomicAdd(M + (size_t)rr * OUT_DIM + cc, v);
        }
    } else {
        // ---- Mp: 768 warps, 3 outputs per warp; diagonal added directly.
        int lane = t & 31, warp = t >> 5;
        int w = (b - GEMM_BLOCKS) * 8 + warp;   // 0..767
        int idx0 = w * 3;
        int m = idx0 / N_NODES, n0 = idx0 % N_NODES;  // same m across the 3
        const float4* A  = (const float4*)(x1 + (size_t)m * DIM);
        const float4* B0 = (const float4*)(x2 + (size_t)n0 * DIM);
        const float4* C  = (const float4*)g_cn;
        float s0 = 0.f, s1 = 0.f, s2 = 0.f;
#pragma unroll
        for (int i = 0; i < 8; i++) {
            int k = i * 32 + lane;
            float4 a = A[k], c = C[k];
            a.x *= c.x; a.y *= c.y; a.z *= c.z; a.w *= c.w;
            float4 b0 = B0[k], b1 = B0[256 + k], b2 = B0[512 + k];
            s0 += a.x * b0.x + a.y * b0.y + a.z * b0.z + a.w * b0.w;
            s1 += a.x * b1.x + a.y * b1.y + a.z * b1.z + a.w * b1.w;
            s2 += a.x * b2.x + a.y * b2.y + a.z * b2.z + a.w * b2.w;
        }
#pragma unroll
        for (int o = 16; o; o >>= 1) {
            s0 += __shfl_xor_sync(0xffffffffu, s0, o);
            s1 += __shfl_xor_sync(0xffffffffu, s1, o);
            s2 += __shfl_xor_sync(0xffffffffu, s2, o);
        }
        if (lane == 0) {
            // M[a, a] += Mp.flat[a]  (M zeroed by k_coeff; diagonal may also
            // receive edge-scatter hits, hence atomicAdd)
            atomicAdd(M + (size_t)(idx0 + 0) * (OUT_DIM + 1), softplus_act(s0));
            atomicAdd(M + (size_t)(idx0 + 1) * (OUT_DIM + 1), softplus_act(s1));
            atomicAdd(M + (size_t)(idx0 + 2) * (OUT_DIM + 1), softplus_act(s2));
        }
    }
}

extern "C" void kernel_launch(void* const* d_in, const int* in_sizes, int n_in,
                              void* d_out, int out_size) {
    const float* x1  = (const float*)d_in[0];
    const float* x2  = (const float*)d_in[1];
    const float* ef1 = (const float*)d_in[2];
    const float* ef2 = (const float*)d_in[3];
    const float* gw  = (const float*)d_in[4];
    const float* Wn  = (const float*)d_in[5];
    const float* bn  = (const float*)d_in[6];
    const float* We  = (const float*)d_in[7];
    const float* be  = (const float*)d_in[8];
    const int*   ei1 = (const int*)d_in[9];
    const int*   ei2 = (const int*)d_in[10];
    float* M = (float*)d_out;

    k_coeff<<<CB, CT>>>(Wn, bn, We, be, gw, (float4*)M);
    k_main<<<MAIN_BLOCKS, 256>>>(ef1, ef2, x1, x2, ei1, ei2, M);
}